// round 4
// baseline (speedup 1.0000x reference)
#include <cuda_runtime.h>
#include <math.h>

// ---------------------------------------------------------------------------
// G_OracleAD: enc-LSTM(+attn pool) -> spatial attention -> dec-LSTM(+readouts)
// B=32 N=64 L=128 H=128  BN=2048  4H=512
// d_out layout (fp32): recon[2048*128] | pred[2048] | c_star[2048*128] | A[32*64*64]
// ---------------------------------------------------------------------------

#define BN_   2048
#define L_    128
#define H_    128
#define G4_   512          // 4*H
#define R_    16           // rows per CTA
#define NCTA_ (BN_ / R_)   // 128
#define THR_  512

// device scratch (no allocation allowed)
__device__ float4 g_encWhhP[32 * G4_];   // packed transposed enc_W_hh
__device__ float4 g_decWhhP[32 * G4_];
__device__ float4 g_decWihP[32 * G4_];
__device__ float  g_c[BN_ * H_];         // pooled encoder context
__device__ float  g_cstar[BN_ * H_];     // spatial-attention output

__device__ __forceinline__ float sig_(float x) {
    return __fdividef(1.f, 1.f + __expf(-x));
}
__device__ __forceinline__ float tanh_(float x) {
    return 1.f - __fdividef(2.f, __expf(2.f * x) + 1.f);
}
__device__ __forceinline__ float warp_sum(float v) {
    #pragma unroll
    for (int o = 16; o; o >>= 1) v += __shfl_xor_sync(0xffffffffu, v, o);
    return v;
}

// pack W[512,128] row-major -> P[kb*512 + t] = float4(W[t][4kb..4kb+3])
__global__ void pack_kernel(const float* __restrict__ encWhh,
                            const float* __restrict__ decWhh,
                            const float* __restrict__ decWih) {
    int idx = blockIdx.x * blockDim.x + threadIdx.x;
    if (idx >= 32 * G4_) return;
    int kb = idx >> 9;
    int t  = idx & 511;
    int s  = t * 128 + kb * 4;
    g_encWhhP[idx] = make_float4(encWhh[s], encWhh[s+1], encWhh[s+2], encWhh[s+3]);
    g_decWhhP[idx] = make_float4(decWhh[s], decWhh[s+1], decWhh[s+2], decWhh[s+3]);
    g_decWihP[idx] = make_float4(decWih[s], decWih[s+1], decWih[s+2], decWih[s+3]);
}

// ---------------------------------------------------------------------------
// Encoder: univariate LSTM over L steps + fused online-softmax attention pool
// smem: gsm[16*512] | hs[16*128] | xs[16*128] | red[64] | fb[16] | wb[16] | zb[16]
// ---------------------------------------------------------------------------
#define ENC_SMEM ((8192 + 2048 + 2048 + 64 + 16 + 16 + 16) * 4)

__global__ __launch_bounds__(THR_, 1)
void encoder_kernel(const float* __restrict__ x,
                    const float* __restrict__ enc_Wih,
                    const float* __restrict__ enc_bih,
                    const float* __restrict__ enc_bhh,
                    const float* __restrict__ pool_w,
                    const float* __restrict__ pool_b) {
    extern __shared__ float sm[];
    float* gsm = sm;                    // [R][512]
    float* hs  = sm + 8192;             // [R][128]
    float* xs  = hs + 2048;             // [R][128]
    float* red = xs + 2048;             // [R][4]
    float* fb  = red + 64;              // [R]
    float* wb  = fb + 16;               // [R]
    float* zb  = wb + 16;               // [R]

    const int tid = threadIdx.x;
    const int rowbase = blockIdx.x * R_;

    for (int i = tid; i < R_ * 128; i += THR_) {
        xs[i] = x[rowbase * 128 + i];
        hs[i] = 0.f;
    }

    // gate-thread constants (thread == gate-row t)
    const float bt  = enc_bih[tid] + enc_bhh[tid];
    const float wih = enc_Wih[tid];
    const float pb  = pool_b[0];

    // elementwise-thread mapping
    const int j  = tid & 127;
    const int rb = tid >> 7;            // 0..3
    const float pwj = pool_w[j];
    float cst[4]  = {0.f, 0.f, 0.f, 0.f};
    float accj[4] = {0.f, 0.f, 0.f, 0.f};
    float mlead = -INFINITY, zlead = 0.f;   // valid for tid<16 (row tid)

    __syncthreads();

    for (int l = 0; l < L_; l++) {
        // ---- phase 1: gate pre-activations (thread = gate-row) ----
        float acc[R_];
        #pragma unroll
        for (int r = 0; r < R_; r++) acc[r] = fmaf(xs[r * 128 + l], wih, bt);
        #pragma unroll 4
        for (int kb = 0; kb < 32; kb++) {
            float4 w = g_encWhhP[kb * G4_ + tid];
            #pragma unroll
            for (int r = 0; r < R_; r++) {
                float4 h4 = *reinterpret_cast<const float4*>(&hs[r * 128 + kb * 4]);
                acc[r] = fmaf(w.x, h4.x, acc[r]);
                acc[r] = fmaf(w.y, h4.y, acc[r]);
                acc[r] = fmaf(w.z, h4.z, acc[r]);
                acc[r] = fmaf(w.w, h4.w, acc[r]);
            }
        }
        #pragma unroll
        for (int r = 0; r < R_; r++) gsm[r * G4_ + tid] = acc[r];
        __syncthreads();

        // ---- phase 2: elementwise LSTM cell + pool partials ----
        float hval[4];
        #pragma unroll
        for (int p = 0; p < 4; p++) {
            int r = p * 4 + rb;
            float gi = gsm[r * G4_ + j];
            float gf = gsm[r * G4_ + 128 + j];
            float gg = gsm[r * G4_ + 256 + j];
            float go = gsm[r * G4_ + 384 + j];
            float si = sig_(gi), sf = sig_(gf), so = sig_(go);
            float tg = tanh_(gg);
            cst[p] = fmaf(sf, cst[p], si * tg);
            float h = so * tanh_(cst[p]);
            hval[p] = h;
            hs[r * 128 + j] = h;
            float contrib = warp_sum(h * pwj);
            if ((tid & 31) == 0) red[r * 4 + ((tid >> 5) & 3)] = contrib;
        }
        __syncthreads();

        // ---- phase 3: per-row online softmax state (leaders tid<16) ----
        if (tid < 16) {
            float s = red[tid * 4] + red[tid * 4 + 1] + red[tid * 4 + 2] + red[tid * 4 + 3] + pb;
            float mn = fmaxf(mlead, s);
            float f  = __expf(mlead - mn);
            float wg = __expf(s - mn);
            zlead = zlead * f + wg;
            mlead = mn;
            fb[tid] = f;
            wb[tid] = wg;
        }
        __syncthreads();

        // ---- phase 4: weighted accumulation of h into pool acc ----
        #pragma unroll
        for (int p = 0; p < 4; p++) {
            int r = p * 4 + rb;
            accj[p] = fmaf(accj[p], fb[r], wb[r] * hval[p]);
        }
    }

    if (tid < 16) zb[tid] = zlead;
    __syncthreads();
    #pragma unroll
    for (int p = 0; p < 4; p++) {
        int r = p * 4 + rb;
        g_c[(rowbase + r) * 128 + j] = __fdividef(accj[p], zb[r]);
    }
}

// ---------------------------------------------------------------------------
// Spatial self-attention per batch: Q/K/V proj, scores, softmax->A, c_star
// ---------------------------------------------------------------------------
#define ATT_SMEM ((8192 * 4 + 4096) * 4)

__global__ __launch_bounds__(256, 1)
void attn_kernel(const float* __restrict__ Wq, const float* __restrict__ bq,
                 const float* __restrict__ Wk, const float* __restrict__ bk,
                 const float* __restrict__ Wv, const float* __restrict__ bv,
                 float* __restrict__ out_cstar, float* __restrict__ out_A) {
    extern __shared__ float sm[];
    float* c_s = sm;            // [64][128]
    float* q_s = sm + 8192;
    float* k_s = sm + 16384;
    float* v_s = sm + 24576;
    float* sc  = sm + 32768;    // [64][64]
    const int b = blockIdx.x, tid = threadIdx.x;

    for (int i = tid; i < 8192; i += 256) c_s[i] = g_c[b * 8192 + i];
    __syncthreads();

    for (int o = tid; o < 8192; o += 256) {
        int n = o >> 7, d = o & 127;
        float aq = bq[d], ak = bk[d], av = bv[d];
        const float* cr = &c_s[n * 128];
        #pragma unroll 8
        for (int kk = 0; kk < 128; kk++) {
            float cv = cr[kk];
            aq = fmaf(cv, __ldg(&Wq[d * 128 + kk]), aq);
            ak = fmaf(cv, __ldg(&Wk[d * 128 + kk]), ak);
            av = fmaf(cv, __ldg(&Wv[d * 128 + kk]), av);
        }
        q_s[o] = aq; k_s[o] = ak; v_s[o] = av;
    }
    __syncthreads();

    const float scale = 0.08838834764831845f;   // 1/sqrt(128)
    for (int o = tid; o < 4096; o += 256) {
        int n = o >> 6, m = o & 63;
        float s = 0.f;
        #pragma unroll 8
        for (int d = 0; d < 128; d++) s = fmaf(q_s[n * 128 + d], k_s[m * 128 + d], s);
        sc[o] = s * scale;
    }
    __syncthreads();

    // softmax rows (warp per row)
    const int warp = tid >> 5, lane = tid & 31;
    for (int n = warp; n < 64; n += 8) {
        float v0 = sc[n * 64 + lane], v1 = sc[n * 64 + 32 + lane];
        float mx = fmaxf(v0, v1);
        #pragma unroll
        for (int o = 16; o; o >>= 1) mx = fmaxf(mx, __shfl_xor_sync(0xffffffffu, mx, o));
        float e0 = __expf(v0 - mx), e1 = __expf(v1 - mx);
        float ss = warp_sum(e0 + e1);
        float inv = 1.f / ss;
        float a0 = e0 * inv, a1 = e1 * inv;
        sc[n * 64 + lane] = a0;
        sc[n * 64 + 32 + lane] = a1;
        out_A[b * 4096 + n * 64 + lane] = a0;
        out_A[b * 4096 + n * 64 + 32 + lane] = a1;
    }
    __syncthreads();

    for (int o = tid; o < 8192; o += 256) {
        int n = o >> 7, d = o & 127;
        float s = 0.f;
        #pragma unroll 8
        for (int m = 0; m < 64; m++) s = fmaf(sc[n * 64 + m], v_s[m * 128 + d], s);
        out_cstar[b * 8192 + o] = s;
        g_cstar[b * 8192 + o]   = s;
    }
}

// ---------------------------------------------------------------------------
// Decoder: constant-input LSTM + fused recon/pred readouts
// smem: gsm[16*512] | hs[16*128] | cs[16*128] | red[64] | red2[64]
// ---------------------------------------------------------------------------
#define DEC_SMEM ((8192 + 2048 + 2048 + 64 + 64) * 4)

__global__ __launch_bounds__(THR_, 1)
void decoder_kernel(const float* __restrict__ dec_bih,
                    const float* __restrict__ dec_bhh,
                    const float* __restrict__ rec_w,  const float* __restrict__ rec_b,
                    const float* __restrict__ pred_w, const float* __restrict__ pred_b,
                    float* __restrict__ out_recon, float* __restrict__ out_pred) {
    extern __shared__ float sm[];
    float* gsm  = sm;                   // [R][512]
    float* hs   = sm + 8192;            // [R][128]
    float* cs   = hs + 2048;            // [R][128]
    float* red  = cs + 2048;            // [R][4]
    float* red2 = red + 64;             // [R][4]

    const int tid = threadIdx.x;
    const int rowbase = blockIdx.x * R_;

    for (int i = tid; i < R_ * 128; i += THR_) {
        cs[i] = g_cstar[rowbase * 128 + i];
        hs[i] = 0.f;
    }
    const float bt = dec_bih[tid] + dec_bhh[tid];
    const float rbv = rec_b[0], pbv = pred_b[0];

    const int j  = tid & 127;
    const int rb = tid >> 7;
    const float rwj = rec_w[j];
    const float pwj = pred_w[j];
    float cst[4] = {0.f, 0.f, 0.f, 0.f};
    __syncthreads();

    // constant input projection: dproj[r] = dec_W_ih[t,:]·c_star[row_r,:] + bt
    float dpr[R_];
    #pragma unroll
    for (int r = 0; r < R_; r++) dpr[r] = bt;
    #pragma unroll 4
    for (int kb = 0; kb < 32; kb++) {
        float4 w = g_decWihP[kb * G4_ + tid];
        #pragma unroll
        for (int r = 0; r < R_; r++) {
            float4 h4 = *reinterpret_cast<const float4*>(&cs[r * 128 + kb * 4]);
            dpr[r] = fmaf(w.x, h4.x, dpr[r]);
            dpr[r] = fmaf(w.y, h4.y, dpr[r]);
            dpr[r] = fmaf(w.z, h4.z, dpr[r]);
            dpr[r] = fmaf(w.w, h4.w, dpr[r]);
        }
    }

    for (int l = 0; l < L_; l++) {
        // ---- phase 1: gates ----
        float acc[R_];
        #pragma unroll
        for (int r = 0; r < R_; r++) acc[r] = dpr[r];
        #pragma unroll 4
        for (int kb = 0; kb < 32; kb++) {
            float4 w = g_decWhhP[kb * G4_ + tid];
            #pragma unroll
            for (int r = 0; r < R_; r++) {
                float4 h4 = *reinterpret_cast<const float4*>(&hs[r * 128 + kb * 4]);
                acc[r] = fmaf(w.x, h4.x, acc[r]);
                acc[r] = fmaf(w.y, h4.y, acc[r]);
                acc[r] = fmaf(w.z, h4.z, acc[r]);
                acc[r] = fmaf(w.w, h4.w, acc[r]);
            }
        }
        #pragma unroll
        for (int r = 0; r < R_; r++) gsm[r * G4_ + tid] = acc[r];
        __syncthreads();

        // ---- phase 2: cell + readout partials ----
        #pragma unroll
        for (int p = 0; p < 4; p++) {
            int r = p * 4 + rb;
            float gi = gsm[r * G4_ + j];
            float gf = gsm[r * G4_ + 128 + j];
            float gg = gsm[r * G4_ + 256 + j];
            float go = gsm[r * G4_ + 384 + j];
            float si = sig_(gi), sf = sig_(gf), so = sig_(go);
            float tg = tanh_(gg);
            cst[p] = fmaf(sf, cst[p], si * tg);
            float h = so * tanh_(cst[p]);
            hs[r * 128 + j] = h;
            float contrib = warp_sum(h * rwj);
            if ((tid & 31) == 0) red[r * 4 + ((tid >> 5) & 3)] = contrib;
            if (l == L_ - 1) {
                float c2 = warp_sum(h * pwj);
                if ((tid & 31) == 0) red2[r * 4 + ((tid >> 5) & 3)] = c2;
            }
        }
        __syncthreads();

        // ---- phase 3: leaders write recon (and pred on last step) ----
        if (tid < 16) {
            float s = red[tid * 4] + red[tid * 4 + 1] + red[tid * 4 + 2] + red[tid * 4 + 3] + rbv;
            out_recon[(rowbase + tid) * 128 + l] = s;
            if (l == L_ - 1) {
                float p2 = red2[tid * 4] + red2[tid * 4 + 1] + red2[tid * 4 + 2] + red2[tid * 4 + 3] + pbv;
                out_pred[rowbase + tid] = p2;
            }
        }
        // next phase-1's __syncthreads orders red reuse
    }
}

// ---------------------------------------------------------------------------
extern "C" void kernel_launch(void* const* d_in, const int* in_sizes, int n_in,
                              void* d_out, int out_size) {
    const float* x        = (const float*)d_in[0];
    const float* enc_Wih  = (const float*)d_in[1];
    const float* enc_Whh  = (const float*)d_in[2];
    const float* enc_bih  = (const float*)d_in[3];
    const float* enc_bhh  = (const float*)d_in[4];
    const float* pool_w   = (const float*)d_in[5];
    const float* pool_b   = (const float*)d_in[6];
    const float* Wq       = (const float*)d_in[7];
    const float* bq       = (const float*)d_in[8];
    const float* Wk       = (const float*)d_in[9];
    const float* bk       = (const float*)d_in[10];
    const float* Wv       = (const float*)d_in[11];
    const float* bv       = (const float*)d_in[12];
    const float* dec_Wih  = (const float*)d_in[13];
    const float* dec_Whh  = (const float*)d_in[14];
    const float* dec_bih  = (const float*)d_in[15];
    const float* dec_bhh  = (const float*)d_in[16];
    const float* rec_w    = (const float*)d_in[17];
    const float* rec_b    = (const float*)d_in[18];
    const float* pred_w   = (const float*)d_in[19];
    const float* pred_b   = (const float*)d_in[20];

    float* out = (float*)d_out;
    float* out_recon = out;                       // 2048*128
    float* out_pred  = out + 262144;              // 2048
    float* out_cstar = out + 264192;              // 2048*128
    float* out_A     = out + 526336;              // 32*64*64

    cudaFuncSetAttribute(encoder_kernel, cudaFuncAttributeMaxDynamicSharedMemorySize, ENC_SMEM);
    cudaFuncSetAttribute(decoder_kernel, cudaFuncAttributeMaxDynamicSharedMemorySize, DEC_SMEM);
    cudaFuncSetAttribute(attn_kernel,    cudaFuncAttributeMaxDynamicSharedMemorySize, ATT_SMEM);

    pack_kernel<<<64, 256>>>(enc_Whh, dec_Whh, dec_Wih);
    encoder_kernel<<<NCTA_, THR_, ENC_SMEM>>>(x, enc_Wih, enc_bih, enc_bhh, pool_w, pool_b);
    attn_kernel<<<32, 256, ATT_SMEM>>>(Wq, bq, Wk, bk, Wv, bv, out_cstar, out_A);
    decoder_kernel<<<NCTA_, THR_, DEC_SMEM>>>(dec_bih, dec_bhh, rec_w, rec_b,
                                              pred_w, pred_b, out_recon, out_pred);
}